// round 11
// baseline (speedup 1.0000x reference)
#include <cuda_runtime.h>

// ---------------- problem constants ----------------
#define NB      4096
#define NNOTES  48
#define NF      256
#define NU      256
#define NG      1024      // 4 * NU (i,f,g,o)
#define K0TOT   516       // padded ih0 (260, last row zero) + hh0 (256)
#define K1TOT   512       // ih1 (256) + hh1 (256)
#define KC      4         // K rows per pipeline chunk
#define NSTAGE  3
#define MROWS   16        // batch rows per CTA (2 CTAs per SM)
#define NCTA    (NB / MROWS)   // 256
#define NTHR    512
#define ASTR    20        // transposed-A row stride (16 rows + 4 pad; 80B = mult of 16B)

typedef unsigned long long u64;

// ---------------- device scratch (static, allocation-guard-safe) ----------------
__device__ __align__(16) float g_W0[K0TOT * NG];   // [k][gatecol] layer 0 (ih pad ++ hh)
__device__ __align__(16) float g_W1[K1TOT * NG];   // [k][gatecol] layer 1 (ih ++ hh)
__device__ __align__(16) float g_b0[NG];
__device__ __align__(16) float g_b1[NG];
__device__ __align__(16) float g_c0[NB * NU];      // layer-0 cell state (L2-resident)
__device__ __align__(16) float g_c1[NB * NU];      // layer-1 cell state

// ---------------- helpers ----------------
__device__ __forceinline__ u64 pack2(float x) {
    u64 r;
    asm("mov.b64 %0, {%1, %1};" : "=l"(r) : "r"(__float_as_uint(x)));
    return r;
}
__device__ __forceinline__ u64 pack2f(float lo, float hi) {
    u64 r;
    asm("mov.b64 %0, {%1, %2};" : "=l"(r) : "r"(__float_as_uint(lo)), "r"(__float_as_uint(hi)));
    return r;
}
__device__ __forceinline__ void fma2(u64& acc, u64 a, u64 b) {
    asm("fma.rn.f32x2 %0, %1, %2, %0;" : "+l"(acc) : "l"(a), "l"(b));
}
__device__ __forceinline__ void unpack2(u64 v, float& lo, float& hi) {
    unsigned int a, b;
    asm("mov.b64 {%0, %1}, %2;" : "=r"(a), "=r"(b) : "l"(v));
    lo = __uint_as_float(a);
    hi = __uint_as_float(b);
}
__device__ __forceinline__ float sigf(float x) {
    return 1.0f / (1.0f + expf(-x));
}
__device__ __forceinline__ void cp16(unsigned dst, const float* src) {
    asm volatile("cp.async.ca.shared.global [%0], [%1], 16;" :: "r"(dst), "l"(src) : "memory");
}
__device__ __forceinline__ void cp_commit() {
    asm volatile("cp.async.commit_group;" ::: "memory");
}
__device__ __forceinline__ void cp_wait1() {
    asm volatile("cp.async.wait_group 1;" ::: "memory");
}

// ---------------- prep: transpose + concatenate weights, combine biases ----------------
__global__ void prep_kernel(const float* __restrict__ W_ih0, const float* __restrict__ W_hh0,
                            const float* __restrict__ b_ih0, const float* __restrict__ b_hh0,
                            const float* __restrict__ W_ih1, const float* __restrict__ W_hh1,
                            const float* __restrict__ b_ih1, const float* __restrict__ b_hh1) {
    int tid = blockIdx.x * blockDim.x + threadIdx.x;
    int stride = gridDim.x * blockDim.x;
    for (int i = tid; i < K0TOT * NG; i += stride) {
        int k = i / NG, j = i - k * NG;
        float v;
        if (k < 259)       v = W_ih0[j * 259 + k];    // original IN0 = 259
        else if (k == 259) v = 0.f;                   // pad row (x[259] = 0 too)
        else               v = W_hh0[j * 256 + (k - 260)];
        g_W0[i] = v;
    }
    for (int i = tid; i < K1TOT * NG; i += stride) {
        int k = i / NG, j = i - k * NG;
        g_W1[i] = (k < 256) ? W_ih1[j * 256 + k] : W_hh1[j * 256 + (k - 256)];
    }
    for (int i = tid; i < NG; i += stride) {
        g_b0[i] = b_ih0[i] + b_hh0[i];
        g_b1[i] = b_ih1[i] + b_hh1[i];
    }
}

// ---------------- GEMM over one layer (concatenated ih++hh K range) ----------------
// Thread (rg, ug): rows rg*8..rg*8+7 (f32x2 lanes = row pairs), unit ug, all 4 gates.
// A operands TRANSPOSED in smem: A[k][row], row stride ASTR; loaded as native u64
// register pairs (no packing MOVs on the A side).
// W staged via 3-stage cp.async pipeline, KC k-rows per chunk (2 cp16/thread).
__device__ __forceinline__ void gemm_layer(
    u64 (&acc)[4][4],
    const float* A0, const float* A1, int swChunk,   // A source switches at chunk swChunk
    const float* __restrict__ Wg, int nchunks,
    const float* sh_w, unsigned sw_u32, int tid, int rg8, int ug)
{
    // prologue: stage chunks 0 and 1 (1024 float4s per chunk, 512 threads -> 2 each)
#pragma unroll
    for (int p = 0; p < 2; p++) {
        unsigned d = sw_u32 + (unsigned)(p * (KC * NG) + tid * 4) * 4u;
        const float* s = Wg + p * (KC * NG) + tid * 4;
        cp16(d, s);
        cp16(d + 512 * 16, s + 512 * 4);
        cp_commit();
    }
    int stage = 0, stage2 = 2;   // stage of chunk ci, and of chunk ci+2
    for (int ci = 0; ci < nchunks; ci++) {
        cp_wait1();              // chunk ci (and older) arrived for THIS thread's copies
        __syncthreads();         // all threads' copies of chunk ci visible; stage2 free
        if (ci + 2 < nchunks) {
            unsigned d = sw_u32 + (unsigned)(stage2 * (KC * NG) + tid * 4) * 4u;
            const float* s = Wg + (size_t)(ci + 2) * (KC * NG) + tid * 4;
            cp16(d, s);
            cp16(d + 512 * 16, s + 512 * 4);
        }
        cp_commit();             // always commit (empty groups keep the count consistent)

        const float* wb = sh_w + stage * (KC * NG) + ug;
        const float* ab = (ci < swChunk ? A0 + ci * (KC * ASTR)
                                        : A1 + (ci - swChunk) * (KC * ASTR)) + rg8;
#pragma unroll
        for (int kk = 0; kk < KC; kk++) {
            // rows rg8..rg8+7 as 4 native u64 pairs (one LDS.128 + one LDS.128)
            ulonglong2 av0 = *(const ulonglong2*)(ab + kk * ASTR);      // rows 0-3 (bcast)
            ulonglong2 av1 = *(const ulonglong2*)(ab + kk * ASTR + 4);  // rows 4-7
            const float* wr = wb + kk * NG;
            u64 wi = pack2(wr[0]);
            u64 wf = pack2(wr[256]);
            u64 wg = pack2(wr[512]);
            u64 wo = pack2(wr[768]);
            fma2(acc[0][0], av0.x, wi); fma2(acc[1][0], av0.y, wi);
            fma2(acc[2][0], av1.x, wi); fma2(acc[3][0], av1.y, wi);
            fma2(acc[0][1], av0.x, wf); fma2(acc[1][1], av0.y, wf);
            fma2(acc[2][1], av1.x, wf); fma2(acc[3][1], av1.y, wf);
            fma2(acc[0][2], av0.x, wg); fma2(acc[1][2], av0.y, wg);
            fma2(acc[2][2], av1.x, wg); fma2(acc[3][2], av1.y, wg);
            fma2(acc[0][3], av0.x, wo); fma2(acc[1][3], av0.y, wo);
            fma2(acc[2][3], av1.x, wo); fma2(acc[3][3], av1.y, wo);
        }
        stage = stage + 1;   if (stage == NSTAGE)  stage = 0;
        stage2 = stage2 + 1; if (stage2 == NSTAGE) stage2 = 0;
    }
}

// ---------------- LSTM cell elementwise ----------------
// Thread owns rows rg8..rg8+7 (4 lane-pairs) and unit ug.
// c comes in prefetched registers, goes out via coalesced STG (L2-resident scratch).
// Writes new h into TRANSPOSED smem layout hT[unit][row].
__device__ __forceinline__ void cell_update(
    u64 (&acc)[4][4], const float (&cin)[8], float* __restrict__ cout_g,
    float* hT, int rg8, int ug)
{
    float hn[8];
#pragma unroll
    for (int rp = 0; rp < 4; rp++) {
        float i0, i1, f0, f1, g0, g1, o0, o1;
        unpack2(acc[rp][0], i0, i1);
        unpack2(acc[rp][1], f0, f1);
        unpack2(acc[rp][2], g0, g1);
        unpack2(acc[rp][3], o0, o1);
        float cn0 = sigf(f0) * cin[2 * rp]     + sigf(i0) * tanhf(g0);
        float cn1 = sigf(f1) * cin[2 * rp + 1] + sigf(i1) * tanhf(g1);
        int r0 = rg8 + 2 * rp;
        cout_g[r0 * NU + ug]       = cn0;   // coalesced STG.32 (warp = 32 consecutive ug)
        cout_g[(r0 + 1) * NU + ug] = cn1;
        hn[2 * rp]     = sigf(o0) * tanhf(cn0);
        hn[2 * rp + 1] = sigf(o1) * tanhf(cn1);
    }
    __syncthreads();   // all GEMM readers of old hT are done
    float4* d = (float4*)(hT + ug * ASTR + rg8);
    d[0] = make_float4(hn[0], hn[1], hn[2], hn[3]);
    d[1] = make_float4(hn[4], hn[5], hn[6], hn[7]);
    __syncthreads();   // new hT visible (output head / next GEMM)
}

// ---------------- main persistent kernel ----------------
__global__ void __launch_bounds__(NTHR, 2)
noteaxis_kernel(const float* __restrict__ feats,
                const float* __restrict__ cond,
                const float* __restrict__ Wout,
                const float* __restrict__ bout,
                float* __restrict__ out)
{
    extern __shared__ float smem[];
    float* sh_w   = smem;                          // 3*4*1024 = 12288 floats
    float* sh_xT  = sh_w + NSTAGE * KC * NG;       // 260*20   = 5200
    float* sh_h0T = sh_xT + 260 * ASTR;            // 256*20   = 5120
    float* sh_h1T = sh_h0T + NU * ASTR;            // 5120
    unsigned sw_u32 = (unsigned)__cvta_generic_to_shared(sh_w);

    int tid = threadIdx.x;
    int rg  = tid >> 8;        // 0..1, warp-uniform
    int ug  = tid & 255;       // unit index
    int rg8 = rg * 8;
    size_t batch0 = (size_t)blockIdx.x * MROWS;

    float* c0g = g_c0 + batch0 * NU;
    float* c1g = g_c1 + batch0 * NU;

    for (int i = tid; i < NU * ASTR; i += NTHR) { sh_h0T[i] = 0.f; sh_h1T[i] = 0.f; }
    // (first gemm iteration's __syncthreads orders the zero-init)

    for (int n = 0; n < NNOTES; n++) {
        // ---- stage x TRANSPOSED: xT[c][r]; coalesced global reads, scattered STS ----
        for (int idx = tid; idx < MROWS * NF; idx += NTHR) {
            int r = idx >> 8;          // NF = 256
            int c = idx & 255;
            sh_xT[c * ASTR + r] = feats[((batch0 + r) * NNOTES + n) * NF + c];
        }
        if (tid < MROWS * 4) {
            int r = tid >> 2, j = tid & 3;
            float v = 0.f;
            if (j < 3 && n > 0) v = cond[((batch0 + r) * NNOTES + (n - 1)) * 3 + j];
            sh_xT[(NF + j) * ASTR + r] = v;   // cols 256..258 = shifted cond, 259 = pad 0
        }
        // (gemm's first-iteration barrier orders these writes before reads)

        u64 acc[4][4];
        float cpre[8];

        // ---- layer 0: gates = [x ++ h0_prev] @ W0^T + b0 ----
#pragma unroll
        for (int rp = 0; rp < 8; rp++)
            cpre[rp] = (n == 0) ? 0.f : c0g[(rg8 + rp) * NU + ug];   // prefetch c (hidden by GEMM)
#pragma unroll
        for (int g = 0; g < 4; g++) {
            u64 bv = pack2(g_b0[g * 256 + ug]);
#pragma unroll
            for (int rp = 0; rp < 4; rp++) acc[rp][g] = bv;
        }
        gemm_layer(acc, sh_xT, sh_h0T, 260 / KC, g_W0, K0TOT / KC,
                   sh_w, sw_u32, tid, rg8, ug);
        cell_update(acc, cpre, c0g, sh_h0T, rg8, ug);

        // ---- layer 1: gates = [h0_new ++ h1_prev] @ W1^T + b1 ----
#pragma unroll
        for (int rp = 0; rp < 8; rp++)
            cpre[rp] = (n == 0) ? 0.f : c1g[(rg8 + rp) * NU + ug];
#pragma unroll
        for (int g = 0; g < 4; g++) {
            u64 bv = pack2(g_b1[g * 256 + ug]);
#pragma unroll
            for (int rp = 0; rp < 4; rp++) acc[rp][g] = bv;
        }
        gemm_layer(acc, sh_h0T, sh_h1T, 256 / KC, g_W1, K1TOT / KC,
                   sh_w, sw_u32, tid, rg8, ug);
        cell_update(acc, cpre, c1g, sh_h1T, rg8, ug);

        // ---- output head: out[b,n,ch] = sigmoid?(h1 . Wout[ch] + bout[ch]) ----
        if (tid < MROWS * 3) {
            int r = tid / 3, ch = tid - r * 3;
            const float* wv = Wout + ch * NU;
            float s = bout[ch];
#pragma unroll 8
            for (int u2 = 0; u2 < NU; u2++)
                s += sh_h1T[u2 * ASTR + r] * wv[u2];
            if (ch < 2) s = sigf(s);
            out[((batch0 + r) * NNOTES + n) * 3 + ch] = s;
        }
        // next staging (xT) is disjoint from h1T; gemm's first barrier gates reuse
    }
}

// ---------------- launch ----------------
extern "C" void kernel_launch(void* const* d_in, const int* in_sizes, int n_in,
                              void* d_out, int out_size)
{
    const float* feats = (const float*)d_in[0];
    const float* cond  = (const float*)d_in[1];
    const float* W_ih0 = (const float*)d_in[2];
    const float* W_hh0 = (const float*)d_in[3];
    const float* b_ih0 = (const float*)d_in[4];
    const float* b_hh0 = (const float*)d_in[5];
    const float* W_ih1 = (const float*)d_in[6];
    const float* W_hh1 = (const float*)d_in[7];
    const float* b_ih1 = (const float*)d_in[8];
    const float* b_hh1 = (const float*)d_in[9];
    const float* W_out = (const float*)d_in[10];
    const float* b_out = (const float*)d_in[11];
    float* out = (float*)d_out;

    prep_kernel<<<264, 256>>>(W_ih0, W_hh0, b_ih0, b_hh0, W_ih1, W_hh1, b_ih1, b_hh1);

    int smem_bytes = (NSTAGE * KC * NG + 260 * ASTR + 2 * NU * ASTR)
                     * (int)sizeof(float);   // 110,912 B -> 2 CTAs/SM
    cudaFuncSetAttribute(noteaxis_kernel,
                         cudaFuncAttributeMaxDynamicSharedMemorySize, smem_bytes);
    noteaxis_kernel<<<NCTA, NTHR, smem_bytes>>>(feats, cond, W_out, b_out, out);
}

// round 12
// speedup vs baseline: 1.2983x; 1.2983x over previous
#include <cuda_runtime.h>

// ---------------- problem constants ----------------
#define NB      4096
#define NNOTES  48
#define NF      256
#define NU      256
#define NG      1024      // 4 * NU (i,f,g,o), interleaved [unit][gate]
#define K0TOT   520       // ih0 (259) + pad(1) + hh0 (256) + pad(4)  -> 65 chunks
#define K1TOT   512       // ih1 (256) + hh1 (256)                    -> 64 chunks
#define KC      8         // K rows per pipeline chunk
#define NSTAGE  2
#define MROWS   32        // batch rows per CTA
#define NTHR    1024
#define ASTR    36        // transposed-A row stride (32 rows + 4 pad)

typedef unsigned long long u64;

// ---------------- device scratch (static, allocation-guard-safe) ----------------
__device__ __align__(16) float g_W0[K0TOT * NG];   // [k][unit*4+gate], pad rows zero
__device__ __align__(16) float g_W1[K1TOT * NG];   // [k][unit*4+gate]
__device__ __align__(16) float g_b0[NG];           // [unit*4+gate]
__device__ __align__(16) float g_b1[NG];
__device__ __align__(16) float g_c0[NB * NU];      // layer-0 cell state (L2-resident)
__device__ __align__(16) float g_c1[NB * NU];      // layer-1 cell state

// ---------------- helpers ----------------
__device__ __forceinline__ u64 pack2(float x) {
    u64 r;
    asm("mov.b64 %0, {%1, %1};" : "=l"(r) : "r"(__float_as_uint(x)));
    return r;
}
__device__ __forceinline__ void fma2(u64& acc, u64 a, u64 b) {
    asm("fma.rn.f32x2 %0, %1, %2, %0;" : "+l"(acc) : "l"(a), "l"(b));
}
__device__ __forceinline__ void unpack2(u64 v, float& lo, float& hi) {
    unsigned int a, b;
    asm("mov.b64 {%0, %1}, %2;" : "=r"(a), "=r"(b) : "l"(v));
    lo = __uint_as_float(a);
    hi = __uint_as_float(b);
}
__device__ __forceinline__ float sigf(float x) {
    return 1.0f / (1.0f + expf(-x));
}
__device__ __forceinline__ void cp16(unsigned dst, const float* src) {
    asm volatile("cp.async.ca.shared.global [%0], [%1], 16;" :: "r"(dst), "l"(src) : "memory");
}
__device__ __forceinline__ void cp_commit() {
    asm volatile("cp.async.commit_group;" ::: "memory");
}
__device__ __forceinline__ void cp_wait1() {
    asm volatile("cp.async.wait_group 1;" ::: "memory");
}

// ---------------- prep: transpose + interleave + concatenate weights ----------------
__global__ void prep_kernel(const float* __restrict__ W_ih0, const float* __restrict__ W_hh0,
                            const float* __restrict__ b_ih0, const float* __restrict__ b_hh0,
                            const float* __restrict__ W_ih1, const float* __restrict__ W_hh1,
                            const float* __restrict__ b_ih1, const float* __restrict__ b_hh1) {
    int tid = blockIdx.x * blockDim.x + threadIdx.x;
    int stride = gridDim.x * blockDim.x;
    for (int i = tid; i < K0TOT * NG; i += stride) {
        int k = i >> 10, j = i & 1023;
        int u = j >> 2, g = j & 3;
        int orow = g * 256 + u;              // original row in [4*NU, K] weight
        float v = 0.f;
        if (k < 259)                 v = W_ih0[orow * 259 + k];
        else if (k >= 260 && k < 516) v = W_hh0[orow * 256 + (k - 260)];
        g_W0[i] = v;                          // rows 259, 516..519 stay zero
    }
    for (int i = tid; i < K1TOT * NG; i += stride) {
        int k = i >> 10, j = i & 1023;
        int u = j >> 2, g = j & 3;
        int orow = g * 256 + u;
        g_W1[i] = (k < 256) ? W_ih1[orow * 256 + k] : W_hh1[orow * 256 + (k - 256)];
    }
    for (int i = tid; i < NG; i += stride) {
        int u = i >> 2, g = i & 3;
        int orow = g * 256 + u;
        g_b0[i] = b_ih0[orow] + b_hh0[orow];
        g_b1[i] = b_ih1[orow] + b_hh1[orow];
    }
}

// ---------------- GEMM over one layer (contiguous concatenated A) ----------------
// Thread (rg, ug): rows rg*8..rg*8+7 (f32x2 lanes = row pairs), unit ug, all 4 gates.
// A transposed in smem: A[k][row], stride ASTR, rows contiguous across x/h segments.
// W interleaved [k][unit*4+gate]: one LDS.128 per kk yields all 4 gate weights.
// W staged via 2-stage cp.async pipeline, KC k-rows per chunk (2 cp16/thread).
__device__ __forceinline__ void gemm_layer(
    u64 (&acc)[4][4],
    const float* A,                      // contiguous [ktot][ASTR]
    const float* __restrict__ Wg, int nchunks,
    const float* sh_w, unsigned sw_u32, int tid, int rg8, int ug)
{
    // prologue: stage chunk 0 into buffer 0 (2048 float4 per chunk, 2 per thread)
    {
        unsigned d = sw_u32 + (unsigned)(tid * 4) * 4u;
        const float* s = Wg + tid * 4;
        cp16(d, s);
        cp16(d + 1024 * 16, s + 1024 * 4);
        cp_commit();
    }
    for (int ci = 0; ci < nchunks; ci++) {
        // issue next chunk first (overlap), then wait for current
        if (ci + 1 < nchunks) {
            unsigned d = sw_u32 + (unsigned)(((ci + 1) & 1) * (KC * NG) + tid * 4) * 4u;
            const float* s = Wg + (size_t)(ci + 1) * (KC * NG) + tid * 4;
            cp16(d, s);
            cp16(d + 1024 * 16, s + 1024 * 4);
        }
        cp_commit();             // always commit (keeps group count consistent)
        cp_wait1();              // chunk ci complete (ci+1 may be in flight)
        __syncthreads();         // all threads' copies of chunk ci visible; old buf free

        const float* wb = sh_w + (ci & 1) * (KC * NG) + ug * 4;
        const float* ab = A + ci * (KC * ASTR) + rg8;
#pragma unroll
        for (int kk = 0; kk < KC; kk++) {
            ulonglong2 av0 = *(const ulonglong2*)(ab + kk * ASTR);      // rows 0-3 (bcast)
            ulonglong2 av1 = *(const ulonglong2*)(ab + kk * ASTR + 4);  // rows 4-7
            float4 w4 = *(const float4*)(wb + kk * NG);                 // gates i,f,g,o
            u64 wi = pack2(w4.x);
            u64 wf = pack2(w4.y);
            u64 wg = pack2(w4.z);
            u64 wo = pack2(w4.w);
            fma2(acc[0][0], av0.x, wi); fma2(acc[1][0], av0.y, wi);
            fma2(acc[2][0], av1.x, wi); fma2(acc[3][0], av1.y, wi);
            fma2(acc[0][1], av0.x, wf); fma2(acc[1][1], av0.y, wf);
            fma2(acc[2][1], av1.x, wf); fma2(acc[3][1], av1.y, wf);
            fma2(acc[0][2], av0.x, wg); fma2(acc[1][2], av0.y, wg);
            fma2(acc[2][2], av1.x, wg); fma2(acc[3][2], av1.y, wg);
            fma2(acc[0][3], av0.x, wo); fma2(acc[1][3], av0.y, wo);
            fma2(acc[2][3], av1.x, wo); fma2(acc[3][3], av1.y, wo);
        }
    }
}

// ---------------- LSTM cell elementwise ----------------
// Thread owns rows rg8..rg8+7 (4 lane-pairs) and unit ug.
// c in prefetched registers -> coalesced STG to L2-resident scratch.
// Writes new h into TRANSPOSED smem layout hT[unit][row].
__device__ __forceinline__ void cell_update(
    u64 (&acc)[4][4], const float (&cin)[8], float* __restrict__ cout_g,
    float* hT, int rg8, int ug)
{
    float hn[8];
#pragma unroll
    for (int rp = 0; rp < 4; rp++) {
        float i0, i1, f0, f1, g0, g1, o0, o1;
        unpack2(acc[rp][0], i0, i1);
        unpack2(acc[rp][1], f0, f1);
        unpack2(acc[rp][2], g0, g1);
        unpack2(acc[rp][3], o0, o1);
        float cn0 = sigf(f0) * cin[2 * rp]     + sigf(i0) * tanhf(g0);
        float cn1 = sigf(f1) * cin[2 * rp + 1] + sigf(i1) * tanhf(g1);
        int r0 = rg8 + 2 * rp;
        cout_g[r0 * NU + ug]       = cn0;   // coalesced STG.32
        cout_g[(r0 + 1) * NU + ug] = cn1;
        hn[2 * rp]     = sigf(o0) * tanhf(cn0);
        hn[2 * rp + 1] = sigf(o1) * tanhf(cn1);
    }
    __syncthreads();   // all GEMM readers of old hT are done
    float4* d = (float4*)(hT + ug * ASTR + rg8);
    d[0] = make_float4(hn[0], hn[1], hn[2], hn[3]);
    d[1] = make_float4(hn[4], hn[5], hn[6], hn[7]);
    __syncthreads();   // new hT visible (output head / next GEMM)
}

// ---------------- main persistent kernel ----------------
__global__ void __launch_bounds__(NTHR, 1)
noteaxis_kernel(const float* __restrict__ feats,
                const float* __restrict__ cond,
                const float* __restrict__ Wout,
                const float* __restrict__ bout,
                float* __restrict__ out)
{
    extern __shared__ float smem[];
    float* sh_w   = smem;                          // 2*8*1024 = 16384 floats
    float* sh_xT  = sh_w + NSTAGE * KC * NG;       // 260 rows
    float* sh_h0T = sh_xT + 260 * ASTR;            // 256 rows (contiguous after xT)
    float* sh_h1T = sh_h0T + NU * ASTR;            // 256 rows (contiguous after h0T)
    unsigned sw_u32 = (unsigned)__cvta_generic_to_shared(sh_w);

    int tid = threadIdx.x;
    int rg  = tid >> 8;        // 0..3, warp-uniform
    int ug  = tid & 255;       // unit index
    int rg8 = rg * 8;
    size_t batch0 = (size_t)blockIdx.x * MROWS;

    float* c0g = g_c0 + batch0 * NU;
    float* c1g = g_c1 + batch0 * NU;

    for (int i = tid; i < 2 * NU * ASTR; i += NTHR) sh_h0T[i] = 0.f;  // h0T + h1T
    // (first gemm chunk's __syncthreads orders the zero-init)

    for (int n = 0; n < NNOTES; n++) {
        // ---- stage x TRANSPOSED: xT[c][r]; coalesced global reads, scattered STS ----
        for (int idx = tid; idx < MROWS * NF; idx += NTHR) {
            int r = idx >> 8;          // NF = 256
            int c = idx & 255;
            sh_xT[c * ASTR + r] = feats[((batch0 + r) * NNOTES + n) * NF + c];
        }
        if (tid < MROWS * 4) {
            int r = tid >> 2, j = tid & 3;
            float v = 0.f;
            if (j < 3 && n > 0) v = cond[((batch0 + r) * NNOTES + (n - 1)) * 3 + j];
            sh_xT[(NF + j) * ASTR + r] = v;   // cols 256..258 = shifted cond, 259 = pad
        }
        // (gemm's first-chunk barrier orders these writes before reads)

        u64 acc[4][4];
        float cpre[8];

        // ---- layer 0: gates = [x ++ h0_prev (++ h1 garbage x zero-W)] @ W0 + b0 ----
#pragma unroll
        for (int rp = 0; rp < 8; rp++)
            cpre[rp] = (n == 0) ? 0.f : c0g[(rg8 + rp) * NU + ug];   // prefetch, hidden by GEMM
        {
            float4 b4 = *(const float4*)(g_b0 + ug * 4);
            u64 bi = pack2(b4.x), bf = pack2(b4.y), bg = pack2(b4.z), bo = pack2(b4.w);
#pragma unroll
            for (int rp = 0; rp < 4; rp++) {
                acc[rp][0] = bi; acc[rp][1] = bf; acc[rp][2] = bg; acc[rp][3] = bo;
            }
        }
        gemm_layer(acc, sh_xT, g_W0, K0TOT / KC, sh_w, sw_u32, tid, rg8, ug);
        cell_update(acc, cpre, c0g, sh_h0T, rg8, ug);

        // ---- layer 1: gates = [h0_new ++ h1_prev] @ W1 + b1 ----
#pragma unroll
        for (int rp = 0; rp < 8; rp++)
            cpre[rp] = (n == 0) ? 0.f : c1g[(rg8 + rp) * NU + ug];
        {
            float4 b4 = *(const float4*)(g_b1 + ug * 4);
            u64 bi = pack2(b4.x), bf = pack2(b4.y), bg = pack2(b4.z), bo = pack2(b4.w);
#pragma unroll
            for (int rp = 0; rp < 4; rp++) {
                acc[rp][0] = bi; acc[rp][1] = bf; acc[rp][2] = bg; acc[rp][3] = bo;
            }
        }
        gemm_layer(acc, sh_h0T, g_W1, K1TOT / KC, sh_w, sw_u32, tid, rg8, ug);
        cell_update(acc, cpre, c1g, sh_h1T, rg8, ug);

        // ---- output head: out[b,n,ch] = sigmoid?(h1 . Wout[ch] + bout[ch]) ----
        if (tid < MROWS * 3) {
            int r = tid / 3, ch = tid - r * 3;
            const float* wv = Wout + ch * NU;
            float s = bout[ch];
#pragma unroll 8
            for (int u2 = 0; u2 < NU; u2++)
                s += sh_h1T[u2 * ASTR + r] * wv[u2];
            if (ch < 2) s = sigf(s);
            out[((batch0 + r) * NNOTES + n) * 3 + ch] = s;
        }
        // next staging (xT) is disjoint from h0T/h1T; gemm's first barrier gates reuse
    }
}

// ---------------- launch ----------------
extern "C" void kernel_launch(void* const* d_in, const int* in_sizes, int n_in,
                              void* d_out, int out_size)
{
    const float* feats = (const float*)d_in[0];
    const float* cond  = (const float*)d_in[1];
    const float* W_ih0 = (const float*)d_in[2];
    const float* W_hh0 = (const float*)d_in[3];
    const float* b_ih0 = (const float*)d_in[4];
    const float* b_hh0 = (const float*)d_in[5];
    const float* W_ih1 = (const float*)d_in[6];
    const float* W_hh1 = (const float*)d_in[7];
    const float* b_ih1 = (const float*)d_in[8];
    const float* b_hh1 = (const float*)d_in[9];
    const float* W_out = (const float*)d_in[10];
    const float* b_out = (const float*)d_in[11];
    float* out = (float*)d_out;

    prep_kernel<<<264, 256>>>(W_ih0, W_hh0, b_ih0, b_hh0, W_ih1, W_hh1, b_ih1, b_hh1);

    int smem_bytes = (NSTAGE * KC * NG + (260 + 2 * NU) * ASTR) * (int)sizeof(float);
    // = (16384 + 27792) * 4 = 176,704 B  -> 1 CTA/SM
    cudaFuncSetAttribute(noteaxis_kernel,
                         cudaFuncAttributeMaxDynamicSharedMemorySize, smem_bytes);
    noteaxis_kernel<<<NB / MROWS, NTHR, smem_bytes>>>(feats, cond, W_out, b_out, out);
}